// round 2
// baseline (speedup 1.0000x reference)
#include <cuda_runtime.h>
#include <cstdint>

#define N_NODES 50000
#define D_IN   600
#define D_H    628     // hidden width (layer1 out)
#define D_HP   640     // padded hidden width (128B-aligned rows)
#define D_OUT  64      // layer2 out

// ---------------- scratch (alloc-free: __device__ globals) ----------------
__device__ float g_buf1[(size_t)N_NODES * D_HP];  // Hs1, later Z1
__device__ float g_buf2[(size_t)N_NODES * D_HP];  // Acc1
__device__ float g_buf3[(size_t)N_NODES * D_OUT]; // Hs2, later Z2
__device__ float g_buf4[(size_t)N_NODES * D_OUT]; // Acc2
__device__ float g_dinv[N_NODES];
__device__ int   g_deg[N_NODES];

// ---------------- degree / dinv ----------------
__global__ void k_count(const int* __restrict__ dst, int E, int* __restrict__ deg) {
    int e = blockIdx.x * blockDim.x + threadIdx.x;
    if (e < E) atomicAdd(&deg[dst[e]], 1);
}

__global__ void k_dinv(const int* __restrict__ deg, float* __restrict__ dinv, int n) {
    int i = blockIdx.x * blockDim.x + threadIdx.x;
    if (i < n) dinv[i] = rsqrtf((float)(deg[i] + 1)); // +1 self loop
}

// ---------------- fused GEMM1: out = dinv[row] * (A @ B) -> Hs and Acc ----------------
// 128x128 tile, 256 threads, 8x8 micro-tile, K-tile 8 with register prefetch.
// B guarded by (k < Kvalid && n < Nvalid) -> 0, so padded output columns are exact zeros.
__global__ __launch_bounds__(256)
void k_gemm1(const float* __restrict__ A, int lda,
             const float* __restrict__ B, int ldb,
             int M, int Kloop, int Kvalid, int Nvalid,
             const float* __restrict__ dinv,
             float* __restrict__ Hs, float* __restrict__ Acc, int ldo)
{
    __shared__ float As[8][128];
    __shared__ float Bs[8][128];
    const int tid = threadIdx.x;
    const int m0 = blockIdx.x * 128;
    const int n0 = blockIdx.y * 128;
    const int tx = tid & 15;   // 16 cols of 8
    const int ty = tid >> 4;   // 16 rows of 8
    const int a_mm = tid >> 1;           // 0..127
    const int a_kq = (tid & 1) << 2;     // 0 or 4
    const int b_kk = tid >> 5;           // 0..7
    const int b_nn = (tid & 31) << 2;    // 0,4,...,124

    float acc[8][8];
#pragma unroll
    for (int i = 0; i < 8; i++)
#pragma unroll
        for (int j = 0; j < 8; j++) acc[i][j] = 0.f;

    const int a_row = m0 + a_mm;
    const bool a_ok = a_row < M;
    const float* Aptr = A + (size_t)a_row * lda + a_kq;

    // prefetch first K-tile
    float4 av = make_float4(0.f, 0.f, 0.f, 0.f);
    float bv[4] = {0.f, 0.f, 0.f, 0.f};
    {
        if (a_ok) av = *(const float4*)(Aptr);
        if (b_kk < Kvalid) {
#pragma unroll
            for (int q = 0; q < 4; q++) {
                int n = n0 + b_nn + q;
                bv[q] = (n < Nvalid) ? B[(size_t)b_kk * ldb + n] : 0.f;
            }
        }
    }

    for (int k0 = 0; k0 < Kloop; k0 += 8) {
        As[a_kq + 0][a_mm] = av.x;
        As[a_kq + 1][a_mm] = av.y;
        As[a_kq + 2][a_mm] = av.z;
        As[a_kq + 3][a_mm] = av.w;
        *(float4*)(&Bs[b_kk][b_nn]) = make_float4(bv[0], bv[1], bv[2], bv[3]);
        __syncthreads();

        // prefetch next tile while computing
        const int kn = k0 + 8;
        float4 av_n = make_float4(0.f, 0.f, 0.f, 0.f);
        float bv_n[4] = {0.f, 0.f, 0.f, 0.f};
        if (kn < Kloop) {
            if (a_ok) av_n = *(const float4*)(Aptr + kn);
            int bk = kn + b_kk;
            if (bk < Kvalid) {
#pragma unroll
                for (int q = 0; q < 4; q++) {
                    int n = n0 + b_nn + q;
                    bv_n[q] = (n < Nvalid) ? B[(size_t)bk * ldb + n] : 0.f;
                }
            }
        }

#pragma unroll
        for (int kk = 0; kk < 8; ++kk) {
            float4 a0 = *(const float4*)(&As[kk][ty * 8]);
            float4 a1 = *(const float4*)(&As[kk][ty * 8 + 4]);
            float4 b0 = *(const float4*)(&Bs[kk][tx * 8]);
            float4 b1 = *(const float4*)(&Bs[kk][tx * 8 + 4]);
            float am[8] = {a0.x, a0.y, a0.z, a0.w, a1.x, a1.y, a1.z, a1.w};
            float bn[8] = {b0.x, b0.y, b0.z, b0.w, b1.x, b1.y, b1.z, b1.w};
#pragma unroll
            for (int i = 0; i < 8; i++)
#pragma unroll
                for (int j = 0; j < 8; j++)
                    acc[i][j] = fmaf(am[i], bn[j], acc[i][j]);
        }
        __syncthreads();
        av = av_n;
#pragma unroll
        for (int q = 0; q < 4; q++) bv[q] = bv_n[q];
    }

    // epilogue: v = acc * dinv[row]; write to both Hs and Acc (Acc = self-loop init)
    const int ldo4 = ldo >> 2;
#pragma unroll
    for (int i = 0; i < 8; i++) {
        int row = m0 + ty * 8 + i;
        if (row < M) {
            float di = dinv[row];
            size_t off = (size_t)row * ldo4 + (n0 >> 2) + tx * 2;
            float4 v0 = make_float4(acc[i][0] * di, acc[i][1] * di,
                                    acc[i][2] * di, acc[i][3] * di);
            float4 v1 = make_float4(acc[i][4] * di, acc[i][5] * di,
                                    acc[i][6] * di, acc[i][7] * di);
            ((float4*)Hs)[off]      = v0;
            ((float4*)Hs)[off + 1]  = v1;
            ((float4*)Acc)[off]     = v0;
            ((float4*)Acc)[off + 1] = v1;
        }
    }
}

// ---------------- GEMM2 (N=64): 128x64 tile, 8x4 micro-tile ----------------
__global__ __launch_bounds__(256)
void k_gemm2(const float* __restrict__ A, int lda,
             const float* __restrict__ B, int ldb,
             int M, int Kloop, int Kvalid,
             const float* __restrict__ dinv,
             float* __restrict__ Hs, float* __restrict__ Acc, int ldo)
{
    __shared__ float As[8][128];
    __shared__ float Bs[8][64];
    const int tid = threadIdx.x;
    const int m0 = blockIdx.x * 128;
    const int tx = tid & 15;
    const int ty = tid >> 4;
    const int a_mm = tid >> 1;
    const int a_kq = (tid & 1) << 2;
    const int b_kk = tid >> 5;
    const int b_nn = tid & 31;

    float acc[8][4];
#pragma unroll
    for (int i = 0; i < 8; i++)
#pragma unroll
        for (int j = 0; j < 4; j++) acc[i][j] = 0.f;

    const int a_row = m0 + a_mm;
    const bool a_ok = a_row < M;
    const float* Aptr = A + (size_t)a_row * lda + a_kq;

    float4 av = make_float4(0.f, 0.f, 0.f, 0.f);
    float bv0 = 0.f, bv1 = 0.f;
    {
        if (a_ok) av = *(const float4*)(Aptr);
        if (b_kk < Kvalid) {
            bv0 = B[(size_t)b_kk * ldb + b_nn];
            bv1 = B[(size_t)b_kk * ldb + b_nn + 32];
        }
    }

    for (int k0 = 0; k0 < Kloop; k0 += 8) {
        As[a_kq + 0][a_mm] = av.x;
        As[a_kq + 1][a_mm] = av.y;
        As[a_kq + 2][a_mm] = av.z;
        As[a_kq + 3][a_mm] = av.w;
        Bs[b_kk][b_nn]      = bv0;
        Bs[b_kk][b_nn + 32] = bv1;
        __syncthreads();

        const int kn = k0 + 8;
        float4 av_n = make_float4(0.f, 0.f, 0.f, 0.f);
        float bv0_n = 0.f, bv1_n = 0.f;
        if (kn < Kloop) {
            if (a_ok) av_n = *(const float4*)(Aptr + kn);
            int bk = kn + b_kk;
            if (bk < Kvalid) {
                bv0_n = B[(size_t)bk * ldb + b_nn];
                bv1_n = B[(size_t)bk * ldb + b_nn + 32];
            }
        }

#pragma unroll
        for (int kk = 0; kk < 8; ++kk) {
            float4 a0 = *(const float4*)(&As[kk][ty * 8]);
            float4 a1 = *(const float4*)(&As[kk][ty * 8 + 4]);
            float4 b4 = *(const float4*)(&Bs[kk][tx * 4]);
            float am[8] = {a0.x, a0.y, a0.z, a0.w, a1.x, a1.y, a1.z, a1.w};
            float bn[4] = {b4.x, b4.y, b4.z, b4.w};
#pragma unroll
            for (int i = 0; i < 8; i++)
#pragma unroll
                for (int j = 0; j < 4; j++)
                    acc[i][j] = fmaf(am[i], bn[j], acc[i][j]);
        }
        __syncthreads();
        av = av_n; bv0 = bv0_n; bv1 = bv1_n;
    }

    const int ldo4 = ldo >> 2;
#pragma unroll
    for (int i = 0; i < 8; i++) {
        int row = m0 + ty * 8 + i;
        if (row < M) {
            float di = dinv[row];
            float4 v = make_float4(acc[i][0] * di, acc[i][1] * di,
                                   acc[i][2] * di, acc[i][3] * di);
            size_t off = (size_t)row * ldo4 + tx;
            ((float4*)Hs)[off]  = v;
            ((float4*)Acc)[off] = v;
        }
    }
}

// ---------------- edge scatter: Acc[dst] += Hs[src] ----------------
template <int LD4, int C4>
__global__ void k_scatter(const float* __restrict__ Hs, float* __restrict__ Acc,
                          const int* __restrict__ src, const int* __restrict__ dst, int E)
{
    int t = blockIdx.x * blockDim.x + threadIdx.x;
    int e = t / C4;
    int c = t - e * C4;
    if (e >= E) return;
    int s = __ldg(&src[e]);
    int d = __ldg(&dst[e]);
    float4 v = ((const float4*)Hs)[(size_t)s * LD4 + c];
    float* p = (float*)(((float4*)Acc) + (size_t)d * LD4 + c);
    atomicAdd(p + 0, v.x);
    atomicAdd(p + 1, v.y);
    atomicAdd(p + 2, v.z);
    atomicAdd(p + 3, v.w);
}

// ---------------- finalize layer 1: Z1 = relu(dinv*Acc + b1), pad cols -> 0 ----------------
__global__ void k_finalize1(const float* __restrict__ Acc, const float* __restrict__ dinv,
                            const float* __restrict__ bias, float* __restrict__ Z)
{
    const int C = D_HP / 4;        // 160
    const int CV = D_H / 4;        // 157 valid
    int t = blockIdx.x * blockDim.x + threadIdx.x;
    int i = t / C;
    int c = t - i * C;
    if (i >= N_NODES) return;
    float4 r = make_float4(0.f, 0.f, 0.f, 0.f);
    if (c < CV) {
        float4 v = ((const float4*)Acc)[(size_t)i * C + c];
        float4 b = ((const float4*)bias)[c];
        float di = dinv[i];
        r.x = fmaxf(fmaf(di, v.x, b.x), 0.f);
        r.y = fmaxf(fmaf(di, v.y, b.y), 0.f);
        r.z = fmaxf(fmaf(di, v.z, b.z), 0.f);
        r.w = fmaxf(fmaf(di, v.w, b.w), 0.f);
    }
    ((float4*)Z)[(size_t)i * C + c] = r;
}

// ---------------- finalize layer 2: Z2 = dinv*Acc + b2 ----------------
__global__ void k_finalize2(const float* __restrict__ Acc, const float* __restrict__ dinv,
                            const float* __restrict__ bias, float* __restrict__ Z)
{
    const int C = D_OUT / 4;       // 16
    int t = blockIdx.x * blockDim.x + threadIdx.x;
    int i = t / C;
    int c = t - i * C;
    if (i >= N_NODES) return;
    float4 v = ((const float4*)Acc)[(size_t)i * C + c];
    float4 b = ((const float4*)bias)[c];
    float di = dinv[i];
    float4 r = make_float4(fmaf(di, v.x, b.x), fmaf(di, v.y, b.y),
                           fmaf(di, v.z, b.z), fmaf(di, v.w, b.w));
    ((float4*)Z)[(size_t)i * C + c] = r;
}

// ---------------- decode: logits[e] = dot(Z2[src], Z2[dst]), 16 lanes/edge ----------------
__global__ void k_decode(const float* __restrict__ Z, const int* __restrict__ src,
                         const int* __restrict__ dst, float* __restrict__ out, int E)
{
    int t = blockIdx.x * blockDim.x + threadIdx.x;
    int e = t >> 4;
    int c = t & 15;
    if (e >= E) return;
    int s = src[e];
    int d = dst[e];
    float4 a = ((const float4*)Z)[(size_t)s * 16 + c];
    float4 b = ((const float4*)Z)[(size_t)d * 16 + c];
    float p = a.x * b.x + a.y * b.y + a.z * b.z + a.w * b.w;
#pragma unroll
    for (int off = 8; off >= 1; off >>= 1)
        p += __shfl_xor_sync(0xffffffffu, p, off);
    if (c == 0) out[e] = p;
}

// ---------------- launch ----------------
extern "C" void kernel_launch(void* const* d_in, const int* in_sizes, int n_in,
                              void* d_out, int out_size)
{
    const float* x  = (const float*)d_in[0];
    const int*   ei = (const int*)d_in[1];
    const float* W1 = (const float*)d_in[2];
    const float* b1 = (const float*)d_in[3];
    const float* W2 = (const float*)d_in[4];
    const float* b2 = (const float*)d_in[5];
    float* out = (float*)d_out;

    const int E = in_sizes[1] / 2;
    const int N = N_NODES;
    const int* src = ei;
    const int* dst = ei + E;

    float *buf1, *buf2, *buf3, *buf4, *dinv;
    int* deg;
    cudaGetSymbolAddress((void**)&buf1, g_buf1);
    cudaGetSymbolAddress((void**)&buf2, g_buf2);
    cudaGetSymbolAddress((void**)&buf3, g_buf3);
    cudaGetSymbolAddress((void**)&buf4, g_buf4);
    cudaGetSymbolAddress((void**)&dinv, g_dinv);
    cudaGetSymbolAddress((void**)&deg,  g_deg);

    // degrees + dinv (recomputed every call: deterministic work)
    cudaMemsetAsync(deg, 0, (size_t)N * sizeof(int), 0);
    k_count<<<(E + 255) / 256, 256>>>(dst, E, deg);
    k_dinv<<<(N + 255) / 256, 256>>>(deg, dinv, N);

    // layer 1: Hs1/Acc1 = dinv * (x @ W1)  [N x 640, cols >=628 exact zeros]
    {
        dim3 grid((N + 127) / 128, D_HP / 128);
        k_gemm1<<<grid, 256>>>(x, D_IN, W1, D_H, N, D_IN, D_IN, D_H,
                               dinv, buf1, buf2, D_HP);
    }
    // edge scatter (157 float4 chunks per edge)
    {
        int total = E * (D_H / 4);
        k_scatter<D_HP / 4, D_H / 4><<<(total + 255) / 256, 256>>>(buf1, buf2, src, dst, E);
    }
    // Z1 = relu(dinv*Acc1 + b1) -> buf1
    {
        int total = N * (D_HP / 4);
        k_finalize1<<<(total + 255) / 256, 256>>>(buf2, dinv, b1, buf1);
    }

    // layer 2: Hs2/Acc2 = dinv * (Z1 @ W2)  [N x 64]; K over padded 640 (pad = zeros)
    {
        k_gemm2<<<(N + 127) / 128, 256>>>(buf1, D_HP, W2, D_OUT, N, D_HP, D_H,
                                          dinv, buf3, buf4, D_OUT);
    }
    {
        int total = E * (D_OUT / 4);
        k_scatter<D_OUT / 4, D_OUT / 4><<<(total + 255) / 256, 256>>>(buf3, buf4, src, dst, E);
    }
    // Z2 = dinv*Acc2 + b2 -> buf3
    {
        int total = N * (D_OUT / 4);
        k_finalize2<<<(total + 255) / 256, 256>>>(buf4, dinv, b2, buf3);
    }
    // decode
    {
        int total = E * 16;
        k_decode<<<(total + 255) / 256, 256>>>(buf3, src, dst, out, E);
    }
}

// round 3
// speedup vs baseline: 1.4736x; 1.4736x over previous
#include <cuda_runtime.h>
#include <cstdint>

#define N_NODES 50000
#define MAX_E   400000
#define D_IN   600
#define D_H    628     // hidden width (layer1 out)
#define D_HP   640     // padded hidden width (128B-aligned rows)
#define D_OUT  64      // layer2 out

// ---------------- scratch (alloc-free: __device__ globals) ----------------
__device__ float g_buf1[(size_t)N_NODES * D_HP];  // Hs1
__device__ float g_buf2[(size_t)N_NODES * D_HP];  // Z1
__device__ float g_buf3[(size_t)N_NODES * D_OUT]; // Hs2
__device__ float g_buf4[(size_t)N_NODES * D_OUT]; // Z2
__device__ float g_dinv[N_NODES];
__device__ int   g_deg[N_NODES];
__device__ int   g_rowstart[N_NODES + 1];
__device__ int   g_cur[N_NODES];
__device__ int   g_adj[MAX_E];

// ---------------- degree / dinv ----------------
__global__ void k_count(const int* __restrict__ dst, int E, int* __restrict__ deg) {
    int e = blockIdx.x * blockDim.x + threadIdx.x;
    if (e < E) atomicAdd(&deg[dst[e]], 1);
}

__global__ void k_dinv(const int* __restrict__ deg, float* __restrict__ dinv, int n) {
    int i = blockIdx.x * blockDim.x + threadIdx.x;
    if (i < n) dinv[i] = rsqrtf((float)(deg[i] + 1)); // +1 self loop
}

// ---------------- exclusive prefix sum of degrees (single block) ----------------
__global__ __launch_bounds__(1024)
void k_scan(const int* __restrict__ deg, int* __restrict__ rowstart, int n) {
    __shared__ int partial[1024];
    const int CH = (n + 1023) / 1024;
    int t = threadIdx.x;
    int t0 = t * CH;
    int s = 0;
    for (int i = 0; i < CH; i++) {
        int idx = t0 + i;
        if (idx < n) s += deg[idx];
    }
    partial[t] = s;
    __syncthreads();
    for (int off = 1; off < 1024; off <<= 1) {
        int v = partial[t];
        int u = (t >= off) ? partial[t - off] : 0;
        __syncthreads();
        partial[t] = v + u;
        __syncthreads();
    }
    int base = (t == 0) ? 0 : partial[t - 1];
    for (int i = 0; i < CH; i++) {
        int idx = t0 + i;
        if (idx < n) { rowstart[idx] = base; base += deg[idx]; }
    }
    if (t == 0) rowstart[n] = partial[1023];
}

// ---------------- CSR fill: adj grouped by dst ----------------
__global__ void k_fill(const int* __restrict__ src, const int* __restrict__ dst, int E,
                       const int* __restrict__ rowstart, int* __restrict__ cur,
                       int* __restrict__ adj) {
    int e = blockIdx.x * blockDim.x + threadIdx.x;
    if (e >= E) return;
    int d = dst[e];
    int p = atomicAdd(&cur[d], 1);
    adj[rowstart[d] + p] = src[e];
}

// ---------------- fused GEMM1: Hs = dinv[row] * (A @ B) ----------------
// 128x128 tile, 256 threads, 8x8 micro-tile, K-tile 8 with register prefetch.
__global__ __launch_bounds__(256)
void k_gemm1(const float* __restrict__ A, int lda,
             const float* __restrict__ B, int ldb,
             int M, int Kloop, int Kvalid, int Nvalid,
             const float* __restrict__ dinv,
             float* __restrict__ Hs, int ldo)
{
    __shared__ float As[8][128];
    __shared__ float Bs[8][128];
    const int tid = threadIdx.x;
    const int m0 = blockIdx.x * 128;
    const int n0 = blockIdx.y * 128;
    const int tx = tid & 15;
    const int ty = tid >> 4;
    const int a_mm = tid >> 1;
    const int a_kq = (tid & 1) << 2;
    const int b_kk = tid >> 5;
    const int b_nn = (tid & 31) << 2;

    float acc[8][8];
#pragma unroll
    for (int i = 0; i < 8; i++)
#pragma unroll
        for (int j = 0; j < 8; j++) acc[i][j] = 0.f;

    const int a_row = m0 + a_mm;
    const bool a_ok = a_row < M;
    const float* Aptr = A + (size_t)a_row * lda + a_kq;

    float4 av = make_float4(0.f, 0.f, 0.f, 0.f);
    float bv[4] = {0.f, 0.f, 0.f, 0.f};
    {
        if (a_ok) av = *(const float4*)(Aptr);
        if (b_kk < Kvalid) {
#pragma unroll
            for (int q = 0; q < 4; q++) {
                int n = n0 + b_nn + q;
                bv[q] = (n < Nvalid) ? B[(size_t)b_kk * ldb + n] : 0.f;
            }
        }
    }

    for (int k0 = 0; k0 < Kloop; k0 += 8) {
        As[a_kq + 0][a_mm] = av.x;
        As[a_kq + 1][a_mm] = av.y;
        As[a_kq + 2][a_mm] = av.z;
        As[a_kq + 3][a_mm] = av.w;
        *(float4*)(&Bs[b_kk][b_nn]) = make_float4(bv[0], bv[1], bv[2], bv[3]);
        __syncthreads();

        const int kn = k0 + 8;
        float4 av_n = make_float4(0.f, 0.f, 0.f, 0.f);
        float bv_n[4] = {0.f, 0.f, 0.f, 0.f};
        if (kn < Kloop) {
            if (a_ok) av_n = *(const float4*)(Aptr + kn);
            int bk = kn + b_kk;
            if (bk < Kvalid) {
#pragma unroll
                for (int q = 0; q < 4; q++) {
                    int n = n0 + b_nn + q;
                    bv_n[q] = (n < Nvalid) ? B[(size_t)bk * ldb + n] : 0.f;
                }
            }
        }

#pragma unroll
        for (int kk = 0; kk < 8; ++kk) {
            float4 a0 = *(const float4*)(&As[kk][ty * 8]);
            float4 a1 = *(const float4*)(&As[kk][ty * 8 + 4]);
            float4 b0 = *(const float4*)(&Bs[kk][tx * 8]);
            float4 b1 = *(const float4*)(&Bs[kk][tx * 8 + 4]);
            float am[8] = {a0.x, a0.y, a0.z, a0.w, a1.x, a1.y, a1.z, a1.w};
            float bn[8] = {b0.x, b0.y, b0.z, b0.w, b1.x, b1.y, b1.z, b1.w};
#pragma unroll
            for (int i = 0; i < 8; i++)
#pragma unroll
                for (int j = 0; j < 8; j++)
                    acc[i][j] = fmaf(am[i], bn[j], acc[i][j]);
        }
        __syncthreads();
        av = av_n;
#pragma unroll
        for (int q = 0; q < 4; q++) bv[q] = bv_n[q];
    }

    const int ldo4 = ldo >> 2;
#pragma unroll
    for (int i = 0; i < 8; i++) {
        int row = m0 + ty * 8 + i;
        if (row < M) {
            float di = dinv[row];
            size_t off = (size_t)row * ldo4 + (n0 >> 2) + tx * 2;
            ((float4*)Hs)[off]     = make_float4(acc[i][0] * di, acc[i][1] * di,
                                                 acc[i][2] * di, acc[i][3] * di);
            ((float4*)Hs)[off + 1] = make_float4(acc[i][4] * di, acc[i][5] * di,
                                                 acc[i][6] * di, acc[i][7] * di);
        }
    }
}

// ---------------- GEMM2 (N=64): 128x64 tile, 8x4 micro-tile ----------------
__global__ __launch_bounds__(256)
void k_gemm2(const float* __restrict__ A, int lda,
             const float* __restrict__ B, int ldb,
             int M, int Kloop, int Kvalid,
             const float* __restrict__ dinv,
             float* __restrict__ Hs, int ldo)
{
    __shared__ float As[8][128];
    __shared__ float Bs[8][64];
    const int tid = threadIdx.x;
    const int m0 = blockIdx.x * 128;
    const int tx = tid & 15;
    const int ty = tid >> 4;
    const int a_mm = tid >> 1;
    const int a_kq = (tid & 1) << 2;
    const int b_kk = tid >> 5;
    const int b_nn = tid & 31;

    float acc[8][4];
#pragma unroll
    for (int i = 0; i < 8; i++)
#pragma unroll
        for (int j = 0; j < 4; j++) acc[i][j] = 0.f;

    const int a_row = m0 + a_mm;
    const bool a_ok = a_row < M;
    const float* Aptr = A + (size_t)a_row * lda + a_kq;

    float4 av = make_float4(0.f, 0.f, 0.f, 0.f);
    float bv0 = 0.f, bv1 = 0.f;
    {
        if (a_ok) av = *(const float4*)(Aptr);
        if (b_kk < Kvalid) {
            bv0 = B[(size_t)b_kk * ldb + b_nn];
            bv1 = B[(size_t)b_kk * ldb + b_nn + 32];
        }
    }

    for (int k0 = 0; k0 < Kloop; k0 += 8) {
        As[a_kq + 0][a_mm] = av.x;
        As[a_kq + 1][a_mm] = av.y;
        As[a_kq + 2][a_mm] = av.z;
        As[a_kq + 3][a_mm] = av.w;
        Bs[b_kk][b_nn]      = bv0;
        Bs[b_kk][b_nn + 32] = bv1;
        __syncthreads();

        const int kn = k0 + 8;
        float4 av_n = make_float4(0.f, 0.f, 0.f, 0.f);
        float bv0_n = 0.f, bv1_n = 0.f;
        if (kn < Kloop) {
            if (a_ok) av_n = *(const float4*)(Aptr + kn);
            int bk = kn + b_kk;
            if (bk < Kvalid) {
                bv0_n = B[(size_t)bk * ldb + b_nn];
                bv1_n = B[(size_t)bk * ldb + b_nn + 32];
            }
        }

#pragma unroll
        for (int kk = 0; kk < 8; ++kk) {
            float4 a0 = *(const float4*)(&As[kk][ty * 8]);
            float4 a1 = *(const float4*)(&As[kk][ty * 8 + 4]);
            float4 b4 = *(const float4*)(&Bs[kk][tx * 4]);
            float am[8] = {a0.x, a0.y, a0.z, a0.w, a1.x, a1.y, a1.z, a1.w};
            float bn[4] = {b4.x, b4.y, b4.z, b4.w};
#pragma unroll
            for (int i = 0; i < 8; i++)
#pragma unroll
                for (int j = 0; j < 4; j++)
                    acc[i][j] = fmaf(am[i], bn[j], acc[i][j]);
        }
        __syncthreads();
        av = av_n; bv0 = bv0_n; bv1 = bv1_n;
    }

    const int ldo4 = ldo >> 2;
#pragma unroll
    for (int i = 0; i < 8; i++) {
        int row = m0 + ty * 8 + i;
        if (row < M) {
            float di = dinv[row];
            size_t off = (size_t)row * ldo4 + tx;
            ((float4*)Hs)[off] = make_float4(acc[i][0] * di, acc[i][1] * di,
                                             acc[i][2] * di, acc[i][3] * di);
        }
    }
}

// ---------------- gather layer 1: Z1 = relu(dinv*(Hs[self] + sum Hs[nbr]) + b1) ----------------
// One CTA of 160 threads per node. Thread c owns float4 column c (c < 157 valid).
__global__ __launch_bounds__(160)
void k_gather1(const float* __restrict__ Hs,
               const int* __restrict__ rowstart, const int* __restrict__ adj,
               const float* __restrict__ dinv, const float* __restrict__ bias,
               float* __restrict__ Z)
{
    const int C  = D_HP / 4;  // 160
    const int CV = D_H / 4;   // 157
    int node = blockIdx.x;
    int c = threadIdx.x;
    int rs = __ldg(&rowstart[node]);
    int re = __ldg(&rowstart[node + 1]);
    bool ok = c < CV;

    float4 acc = make_float4(0.f, 0.f, 0.f, 0.f);
    if (ok) acc = ((const float4*)Hs)[(size_t)node * C + c]; // self loop

    int j = rs;
    for (; j + 1 < re; j += 2) {
        int s0 = __ldg(&adj[j]);
        int s1 = __ldg(&adj[j + 1]);
        if (ok) {
            float4 v0 = ((const float4*)Hs)[(size_t)s0 * C + c];
            float4 v1 = ((const float4*)Hs)[(size_t)s1 * C + c];
            acc.x += v0.x + v1.x; acc.y += v0.y + v1.y;
            acc.z += v0.z + v1.z; acc.w += v0.w + v1.w;
        }
    }
    if (j < re) {
        int s0 = __ldg(&adj[j]);
        if (ok) {
            float4 v0 = ((const float4*)Hs)[(size_t)s0 * C + c];
            acc.x += v0.x; acc.y += v0.y; acc.z += v0.z; acc.w += v0.w;
        }
    }

    float4 r = make_float4(0.f, 0.f, 0.f, 0.f);
    if (ok) {
        float di = __ldg(&dinv[node]);
        float4 b = ((const float4*)bias)[c];
        r.x = fmaxf(fmaf(di, acc.x, b.x), 0.f);
        r.y = fmaxf(fmaf(di, acc.y, b.y), 0.f);
        r.z = fmaxf(fmaf(di, acc.z, b.z), 0.f);
        r.w = fmaxf(fmaf(di, acc.w, b.w), 0.f);
    }
    ((float4*)Z)[(size_t)node * C + c] = r;  // pad cols -> exact zeros
}

// ---------------- gather layer 2: Z2 = dinv*(Hs2[self] + sum Hs2[nbr]) + b2 ----------------
// One warp per node; lane owns float2 column (64 floats = 32 float2).
__global__ __launch_bounds__(256)
void k_gather2(const float* __restrict__ Hs,
               const int* __restrict__ rowstart, const int* __restrict__ adj,
               const float* __restrict__ dinv, const float* __restrict__ bias,
               float* __restrict__ Z, int n)
{
    int warp = (blockIdx.x * blockDim.x + threadIdx.x) >> 5;
    int lane = threadIdx.x & 31;
    if (warp >= n) return;
    int node = warp;
    int rs = __ldg(&rowstart[node]);
    int re = __ldg(&rowstart[node + 1]);

    float2 acc = ((const float2*)Hs)[(size_t)node * 32 + lane];

    int j = rs;
    for (; j + 1 < re; j += 2) {
        int s0 = __ldg(&adj[j]);
        int s1 = __ldg(&adj[j + 1]);
        float2 v0 = ((const float2*)Hs)[(size_t)s0 * 32 + lane];
        float2 v1 = ((const float2*)Hs)[(size_t)s1 * 32 + lane];
        acc.x += v0.x + v1.x; acc.y += v0.y + v1.y;
    }
    if (j < re) {
        int s0 = __ldg(&adj[j]);
        float2 v0 = ((const float2*)Hs)[(size_t)s0 * 32 + lane];
        acc.x += v0.x; acc.y += v0.y;
    }

    float di = __ldg(&dinv[node]);
    float2 b = ((const float2*)bias)[lane];
    float2 r = make_float2(fmaf(di, acc.x, b.x), fmaf(di, acc.y, b.y));
    ((float2*)Z)[(size_t)node * 32 + lane] = r;
}

// ---------------- decode: logits[e] = dot(Z2[src], Z2[dst]), 16 lanes/edge ----------------
__global__ void k_decode(const float* __restrict__ Z, const int* __restrict__ src,
                         const int* __restrict__ dst, float* __restrict__ out, int E)
{
    int t = blockIdx.x * blockDim.x + threadIdx.x;
    int e = t >> 4;
    int c = t & 15;
    if (e >= E) return;
    int s = src[e];
    int d = dst[e];
    float4 a = ((const float4*)Z)[(size_t)s * 16 + c];
    float4 b = ((const float4*)Z)[(size_t)d * 16 + c];
    float p = a.x * b.x + a.y * b.y + a.z * b.z + a.w * b.w;
#pragma unroll
    for (int off = 8; off >= 1; off >>= 1)
        p += __shfl_xor_sync(0xffffffffu, p, off);
    if (c == 0) out[e] = p;
}

// ---------------- launch ----------------
extern "C" void kernel_launch(void* const* d_in, const int* in_sizes, int n_in,
                              void* d_out, int out_size)
{
    const float* x  = (const float*)d_in[0];
    const int*   ei = (const int*)d_in[1];
    const float* W1 = (const float*)d_in[2];
    const float* b1 = (const float*)d_in[3];
    const float* W2 = (const float*)d_in[4];
    const float* b2 = (const float*)d_in[5];
    float* out = (float*)d_out;

    const int E = in_sizes[1] / 2;
    const int N = N_NODES;
    const int* src = ei;
    const int* dst = ei + E;

    float *buf1, *buf2, *buf3, *buf4, *dinv;
    int *deg, *rowstart, *cur, *adj;
    cudaGetSymbolAddress((void**)&buf1, g_buf1);
    cudaGetSymbolAddress((void**)&buf2, g_buf2);
    cudaGetSymbolAddress((void**)&buf3, g_buf3);
    cudaGetSymbolAddress((void**)&buf4, g_buf4);
    cudaGetSymbolAddress((void**)&dinv, g_dinv);
    cudaGetSymbolAddress((void**)&deg,  g_deg);
    cudaGetSymbolAddress((void**)&rowstart, g_rowstart);
    cudaGetSymbolAddress((void**)&cur,  g_cur);
    cudaGetSymbolAddress((void**)&adj,  g_adj);

    // CSR build (keyed by dst) + dinv
    cudaMemsetAsync(deg, 0, (size_t)N * sizeof(int), 0);
    cudaMemsetAsync(cur, 0, (size_t)N * sizeof(int), 0);
    k_count<<<(E + 255) / 256, 256>>>(dst, E, deg);
    k_dinv<<<(N + 255) / 256, 256>>>(deg, dinv, N);
    k_scan<<<1, 1024>>>(deg, rowstart, N);
    k_fill<<<(E + 255) / 256, 256>>>(src, dst, E, rowstart, cur, adj);

    // layer 1: Hs1 = dinv * (x @ W1)  [N x 640, cols >=628 exact zeros]
    {
        dim3 grid((N + 127) / 128, D_HP / 128);
        k_gemm1<<<grid, 256>>>(x, D_IN, W1, D_H, N, D_IN, D_IN, D_H,
                               dinv, buf1, D_HP);
    }
    // Z1 = relu(dinv*(self + neighbor sum) + b1)
    k_gather1<<<N, 160>>>(buf1, rowstart, adj, dinv, b1, buf2);

    // layer 2: Hs2 = dinv * (Z1 @ W2)  [N x 64]; K over padded 640 (pad = zeros)
    k_gemm2<<<(N + 127) / 128, 256>>>(buf2, D_HP, W2, D_OUT, N, D_HP, D_H,
                                      dinv, buf3, D_OUT);
    // Z2 = dinv*(self + neighbor sum) + b2
    k_gather2<<<(N * 32 + 255) / 256, 256>>>(buf3, rowstart, adj, dinv, b2, buf4, N);

    // decode
    k_decode<<<(E * 16 + 255) / 256, 256>>>(buf4, src, dst, out, E);
}